// round 9
// baseline (speedup 1.0000x reference)
#include <cuda_runtime.h>

#define NB 65536
#define NL 1024
#define FULLM 0xFFFFFFFFu
#define ROW_BLOCKS 8192
#define FIN_BLOCKS 256

// ---------------- device scratch (module-initialized; last finisher restores state) ----------------
__device__ float  g_e[NB];                        // per-row raw energy S1/S2
__device__ double g_acc[3] = {0.0, 0.0, 0.0};     // [0]=wave, [1]=cls nll, [2]=penalty
__device__ int    g_cnt = 0;                      // n_valid labels
__device__ int    g_maxo = (int)0x80000000;       // global max, ordered-int encoding
__device__ int    g_done = 0;                     // k_row completion ticket
__device__ int    g_t2   = 0;                     // finisher completion ticket

__device__ __forceinline__ int   f2o(float f){ int i=__float_as_int(f); return i>=0 ? i : (i^0x7FFFFFFF); }
__device__ __forceinline__ float o2f(int i){ return __int_as_float(i>=0 ? i : (i^0x7FFFFFFF)); }

__global__ void __launch_bounds__(256) k_all(const float4* __restrict__ wave,
                                             const float*  __restrict__ depth,
                                             const float4* __restrict__ logits,
                                             const longlong2* __restrict__ lab2,
                                             float* __restrict__ out){
    const int lane = threadIdx.x & 31;
    const int wid  = threadIdx.x >> 5;

    if (blockIdx.x < ROW_BLOCKS) {
        // ================= k_row: warp-per-row streaming pass (proven shape) =================
        const int row = blockIdx.x * 8 + wid;
        const float4* rp = wave + (size_t)row * 256u;

        float4 r[8];
        #pragma unroll
        for (int i = 0; i < 8; i++) r[i] = __ldcs(&rp[32*i + lane]);   // read-once

        const float tpos = __ldg(&depth[row]) * 10.0f;   // (2*d/4000)*20000

        float ws = 0.0f, S1 = 0.0f, S2 = 0.0f;
        float mx = -3.402823466e+38f;

        #pragma unroll
        for (int i = 0; i < 8; i++) {
            float4 v = r[i];
            mx = fmaxf(mx, fmaxf(fmaxf(v.x, v.y), fmaxf(v.z, v.w)));

            // Gaussian window (sigma = 5): only threads near tpos pay for exp
            float j = (float)(128*i + 4*lane);
            if (fabsf(j + 1.5f - tpos) < 51.5f) {
                float d0 = j        - tpos;  float e0 = __expf(-0.02f*d0*d0);
                float d1 = j + 1.0f - tpos;  float e1 = __expf(-0.02f*d1*d1);
                float d2 = j + 2.0f - tpos;  float e2 = __expf(-0.02f*d2*d2);
                float d3 = j + 3.0f - tpos;  float e3 = __expf(-0.02f*d3*d3);
                S2 += (e0 + e1) + (e2 + e3);
                S1 += fmaf(v.x*v.x, e0, fmaf(v.y*v.y, e1, fmaf(v.z*v.z, e2, v.w*v.w*e3)));
            }

            // neighbors for the second difference
            float lm = __shfl_up_sync  (FULLM, v.w, 1);
            float rn = __shfl_down_sync(FULLM, v.x, 1);
            float lmB = (i > 0) ? __shfl_sync(FULLM, r[i-1].w, 31) : 0.0f;
            float rnB = (i < 7) ? __shfl_sync(FULLM, r[i+1].x, 0)  : 0.0f;
            if (lane == 0)  lm = lmB;
            if (lane == 31) rn = rnB;

            float d0 = (i == 0 && lane == 0)  ? (v.y - v.x)
                                              : (fmaf(-2.0f, v.x, v.y) + lm);
            float d1 = fmaf(-2.0f, v.y, v.z) + v.x;
            float d2 = fmaf(-2.0f, v.z, v.w) + v.y;
            float d3 = (i == 7 && lane == 31) ? (v.z - v.w)
                                              : (fmaf(-2.0f, v.w, rn) + v.z);
            ws += fmaf(d0, d0, fmaf(d1, d1, fmaf(d2, d2, d3*d3)));
        }
        ws *= 9900.0f * 9900.0f;   // (1/DT^2 - C^2/DX^2)^2

        #pragma unroll
        for (int o = 16; o > 0; o >>= 1) {
            ws += __shfl_xor_sync(FULLM, ws, o);
            S1 += __shfl_xor_sync(FULLM, S1, o);
            S2 += __shfl_xor_sync(FULLM, S2, o);
            mx  = fmaxf(mx, __shfl_xor_sync(FULLM, mx, o));
        }

        __shared__ float sw[8], sm[8];
        if (lane == 0) {
            g_e[row] = S1 / S2;
            sw[wid] = ws;  sm[wid] = mx;
        }
        __syncthreads();
        if (threadIdx.x == 0) {
            float W = sw[0], M = sm[0];
            #pragma unroll
            for (int i = 1; i < 8; i++) { W += sw[i]; M = fmaxf(M, sm[i]); }
            atomicAdd(&g_acc[0], (double)W);
            atomicMax(&g_maxo, f2o(M));
            __threadfence();
            atomicAdd(&g_done, 1);      // release: this block's results are visible
        }
    } else {
        // ================= finisher: CE overlapped, penalty after k_row drains =================
        const int row = (blockIdx.x - ROW_BLOCKS) * 256 + threadIdx.x;   // 1 row/thread

        // --- phase 1 (independent of k_row): load + CE + argmax ---
        float4 lg = logits[row];
        longlong2 lp = lab2[row >> 1];
        long long lab = (row & 1) ? lp.y : lp.x;

        int am = 0; float bm = lg.x;                 // first-occurrence argmax
        if (lg.y > bm) { bm = lg.y; am = 1; }
        if (lg.z > bm) { bm = lg.z; am = 2; }
        if (lg.w > bm) { bm = lg.w; am = 3; }

        float cS = 0.0f; int cnt = 0;
        if (lab != -1ll) {
            float se = __expf(lg.x - bm) + __expf(lg.y - bm)
                     + __expf(lg.z - bm) + __expf(lg.w - bm);
            int li = (int)lab;
            float sel = (li == 0) ? lg.x : (li == 1) ? lg.y : (li == 2) ? lg.z : lg.w;
            cS = bm + __logf(se) - sel;
            cnt = 1;
        }

        // --- phase 2: wait for all k_row blocks ---
        if (threadIdx.x == 0) {
            int d;
            do {
                asm volatile("ld.global.acquire.gpu.b32 %0, [%1];"
                             : "=r"(d) : "l"(&g_done) : "memory");
                if (d < ROW_BLOCKS) __nanosleep(128);
            } while (d < ROW_BLOCKS);
        }
        __syncthreads();

        // --- phase 3: penalty using gmax + g_e ---
        const float gmax = o2f(*(volatile int*)&g_maxo);
        const float inv  = 1.0f / (20.0f * gmax);
        float e = g_e[row] * inv;
        float pS;
        if (am >= 2) { float d = 0.1f - e; pS = (e < 0.1f) ? d*d : 0.0f; }
        else         { float d = e - 0.5f; pS = (e > 0.5f) ? d*d : 0.0f; }

        #pragma unroll
        for (int o = 16; o > 0; o >>= 1) {
            cS  += __shfl_xor_sync(FULLM, cS, o);
            pS  += __shfl_xor_sync(FULLM, pS, o);
            cnt += __shfl_xor_sync(FULLM, cnt, o);
        }
        __shared__ float scs[8], sps[8]; __shared__ int sn[8];
        if (lane == 0) { scs[wid]=cS; sps[wid]=pS; sn[wid]=cnt; }
        __syncthreads();
        if (threadIdx.x == 0) {
            #pragma unroll
            for (int i = 1; i < 8; i++) { cS+=scs[i]; pS+=sps[i]; cnt+=sn[i]; }
            atomicAdd(&g_acc[1], (double)cS);
            atomicAdd(&g_acc[2], (double)pS);
            atomicAdd(&g_cnt, cnt);

            __threadfence();
            int tk = atomicAdd(&g_t2, 1);
            if (tk == FIN_BLOCKS - 1) {              // last finisher: output + reset
                double wave = g_acc[0] * (1.0 / ((double)NB * (double)NL));
                double cls  = (g_cnt > 0) ? (g_acc[1] / (double)g_cnt) : 0.0;
                double phys = g_acc[2] * (1.0 / (double)NB);
                out[0] = (float)(cls + 0.1 * wave + 0.1 * phys);
                out[1] = (float)cls;
                out[2] = (float)wave;
                out[3] = (float)phys;
                // reset-after-use: leave globals in initial state for next replay
                g_acc[0] = 0.0; g_acc[1] = 0.0; g_acc[2] = 0.0;
                g_cnt = 0; g_maxo = (int)0x80000000;
                g_done = 0; g_t2 = 0;
            }
        }
    }
}

// ---------------- launch ----------------
extern "C" void kernel_launch(void* const* d_in, const int* in_sizes, int n_in,
                              void* d_out, int out_size){
    const float4*    wave   = (const float4*)d_in[0];
    const float4*    logits = (const float4*)d_in[1];
    const float*     depth  = (const float*)d_in[2];
    const longlong2* lab    = (const longlong2*)d_in[3];

    k_all<<<ROW_BLOCKS + FIN_BLOCKS, 256>>>(wave, depth, logits, lab, (float*)d_out);
}

// round 12
// speedup vs baseline: 1.0329x; 1.0329x over previous
#include <cuda_runtime.h>

#define NB 65536
#define NL 1024
#define FULLM 0xFFFFFFFFu

// ---------------- device scratch (module-initialized; last k_fin block restores state) ----------------
__device__ float         g_e[NB];                 // per-row raw energy S1/S2
__device__ unsigned char g_am[NB];                // per-row is_defect flag (argmax>=2)
__device__ double g_acc[3] = {0.0, 0.0, 0.0};     // [0]=wave, [1]=cls nll, [2]=penalty
__device__ int    g_cnt = 0;                      // n_valid labels
__device__ int    g_maxo = (int)0x80000000;       // global max, ordered-int encoding
__device__ int    g_ticket = 0;                   // last-block-done ticket for k_fin

__device__ __forceinline__ int   f2o(float f){ int i=__float_as_int(f); return i>=0 ? i : (i^0x7FFFFFFF); }
__device__ __forceinline__ float o2f(int i){ return __int_as_float(i>=0 ? i : (i^0x7FFFFFFF)); }

// ---------------- K1: warp-per-row streaming pass (R8 mainloop, CE in epilogue) ----------------
// block = 256 threads = 8 warps = 8 rows; grid = 8192.
// Thread `lane` loads float4 indices {32*i + lane}, i=0..7 (coalesced, front-batched).
__global__ void __launch_bounds__(256) k_row(const float4* __restrict__ wave,
                                             const float*  __restrict__ depth,
                                             const float4* __restrict__ logits,
                                             const long long* __restrict__ labels){
    const int lane = threadIdx.x & 31;
    const int wid  = threadIdx.x >> 5;
    const int row  = blockIdx.x * 8 + wid;
    const float4* rp = wave + (size_t)row * 256u;

    float4 r[8];
    #pragma unroll
    for (int i = 0; i < 8; i++) r[i] = __ldcs(&rp[32*i + lane]);   // read-once

    const float tpos = __ldg(&depth[row]) * 10.0f;   // (2*d/4000)*20000

    float ws = 0.0f, S1 = 0.0f, S2 = 0.0f;
    float mx = -3.402823466e+38f;

    #pragma unroll
    for (int i = 0; i < 8; i++) {
        float4 v = r[i];
        mx = fmaxf(mx, fmaxf(fmaxf(v.x, v.y), fmaxf(v.z, v.w)));

        // Gaussian window (sigma = 5): only threads near tpos pay for exp
        float j = (float)(128*i + 4*lane);
        if (fabsf(j + 1.5f - tpos) < 51.5f) {
            float d0 = j        - tpos;  float e0 = __expf(-0.02f*d0*d0);
            float d1 = j + 1.0f - tpos;  float e1 = __expf(-0.02f*d1*d1);
            float d2 = j + 2.0f - tpos;  float e2 = __expf(-0.02f*d2*d2);
            float d3 = j + 3.0f - tpos;  float e3 = __expf(-0.02f*d3*d3);
            S2 += (e0 + e1) + (e2 + e3);
            S1 += fmaf(v.x*v.x, e0, fmaf(v.y*v.y, e1, fmaf(v.z*v.z, e2, v.w*v.w*e3)));
        }

        // neighbors for the second difference
        float lm = __shfl_up_sync  (FULLM, v.w, 1);
        float rn = __shfl_down_sync(FULLM, v.x, 1);
        float lmB = (i > 0) ? __shfl_sync(FULLM, r[i-1].w, 31) : 0.0f;
        float rnB = (i < 7) ? __shfl_sync(FULLM, r[i+1].x, 0)  : 0.0f;
        if (lane == 0)  lm = lmB;
        if (lane == 31) rn = rnB;

        float d0 = (i == 0 && lane == 0)  ? (v.y - v.x)
                                          : (fmaf(-2.0f, v.x, v.y) + lm);
        float d1 = fmaf(-2.0f, v.y, v.z) + v.x;
        float d2 = fmaf(-2.0f, v.z, v.w) + v.y;
        float d3 = (i == 7 && lane == 31) ? (v.z - v.w)
                                          : (fmaf(-2.0f, v.w, rn) + v.z);
        ws += fmaf(d0, d0, fmaf(d1, d1, fmaf(d2, d2, d3*d3)));
    }
    ws *= 9900.0f * 9900.0f;   // (1/DT^2 - C^2/DX^2)^2

    #pragma unroll
    for (int o = 16; o > 0; o >>= 1) {
        ws += __shfl_xor_sync(FULLM, ws, o);
        S1 += __shfl_xor_sync(FULLM, S1, o);
        S2 += __shfl_xor_sync(FULLM, S2, o);
        mx  = fmaxf(mx, __shfl_xor_sync(FULLM, mx, o));
    }

    // epilogue (r[] dead here): energy store + CE + argmax by lane 0 of each warp
    __shared__ float sw[8], sm[8], scc[8];
    __shared__ int   scn[8];
    if (lane == 0) {
        g_e[row] = S1 / S2;

        float4 lg = logits[row];
        long long lab = labels[row];
        int am = 0; float bm = lg.x;                 // first-occurrence argmax
        if (lg.y > bm) { bm = lg.y; am = 1; }
        if (lg.z > bm) { bm = lg.z; am = 2; }
        if (lg.w > bm) { bm = lg.w; am = 3; }
        g_am[row] = (unsigned char)(am >= 2);

        float ce = 0.0f; int valid = 0;
        if (lab != -1ll) {
            float se = __expf(lg.x - bm) + __expf(lg.y - bm)
                     + __expf(lg.z - bm) + __expf(lg.w - bm);
            int li = (int)lab;
            float sel = (li == 0) ? lg.x : (li == 1) ? lg.y : (li == 2) ? lg.z : lg.w;
            ce = bm + __logf(se) - sel;
            valid = 1;
        }
        sw[wid] = ws;  sm[wid] = mx;  scc[wid] = ce;  scn[wid] = valid;
    }
    __syncthreads();
    if (threadIdx.x == 0) {
        float W = sw[0], M = sm[0], C = scc[0]; int N = scn[0];
        #pragma unroll
        for (int i = 1; i < 8; i++) {
            W += sw[i]; C += scc[i]; N += scn[i]; M = fmaxf(M, sm[i]);
        }
        atomicAdd(&g_acc[0], (double)W);
        atomicAdd(&g_acc[1], (double)C);
        atomicAdd(&g_cnt, N);
        atomicMax(&g_maxo, f2o(M));
    }
}

// ---------------- K2: penalty-only + finalize (reads L2-hot g_e/g_am) ----------------
__global__ void __launch_bounds__(256) k_fin(float* __restrict__ out){
    const int t = blockIdx.x * 256 + threadIdx.x;        // 16384 threads, 4 rows each
    const float gmax = o2f(g_maxo);
    const float inv  = 1.0f / (20.0f * gmax);

    float4 e4 = ((const float4*)g_e)[t];                 // rows 4t..4t+3
    uchar4 a4 = ((const uchar4*)g_am)[t];
    const float ev[4] = {e4.x, e4.y, e4.z, e4.w};
    const unsigned char av[4] = {a4.x, a4.y, a4.z, a4.w};

    float pS = 0.0f;
    #pragma unroll
    for (int k = 0; k < 4; k++) {
        float e = ev[k] * inv;
        if (av[k]) { float d = 0.1f - e; pS += (e < 0.1f) ? d*d : 0.0f; }
        else       { float d = e - 0.5f; pS += (e > 0.5f) ? d*d : 0.0f; }
    }

    #pragma unroll
    for (int o = 16; o > 0; o >>= 1)
        pS += __shfl_xor_sync(FULLM, pS, o);
    __shared__ float sps[8];
    int lane = threadIdx.x & 31, wid = threadIdx.x >> 5;
    if (lane == 0) sps[wid] = pS;
    __syncthreads();
    if (threadIdx.x == 0) {
        #pragma unroll
        for (int i = 1; i < 8; i++) pS += sps[i];
        atomicAdd(&g_acc[2], (double)pS);

        __threadfence();
        int tk = atomicAdd(&g_ticket, 1);
        if (tk == gridDim.x - 1) {                       // last block: finalize + reset
            double wave = g_acc[0] * (1.0 / ((double)NB * (double)NL));
            double cls  = (g_cnt > 0) ? (g_acc[1] / (double)g_cnt) : 0.0;
            double phys = g_acc[2] * (1.0 / (double)NB);
            out[0] = (float)(cls + 0.1 * wave + 0.1 * phys);
            out[1] = (float)cls;
            out[2] = (float)wave;
            out[3] = (float)phys;
            // reset-after-use: leave globals in initial state for next replay
            g_acc[0] = 0.0; g_acc[1] = 0.0; g_acc[2] = 0.0;
            g_cnt = 0; g_maxo = (int)0x80000000; g_ticket = 0;
        }
    }
}

// ---------------- launch ----------------
extern "C" void kernel_launch(void* const* d_in, const int* in_sizes, int n_in,
                              void* d_out, int out_size){
    const float4*    wave   = (const float4*)d_in[0];
    const float4*    logits = (const float4*)d_in[1];
    const float*     depth  = (const float*)d_in[2];
    const long long* labels = (const long long*)d_in[3];

    k_row<<<NB/8, 256>>>(wave, depth, logits, labels);
    k_fin<<<NB/1024, 256>>>((float*)d_out);
}